// round 13
// baseline (speedup 1.0000x reference)
#include <cuda_runtime.h>
#include <cstdint>

// Problem dims
#define BB 8192
#define HH 1024
#define EE 8

// GEMM tile: 64x128x32, 128 threads, 4 warps (2 M x 2 N), warp tile 32x64.
// 2 CTAs per SM (96KB smem each) with FULL 2-chunk cp.async slack — isolates
// the cross-CTA-overlap variable that R9 confounded with reduced slack.
#define BM 64
#define BN 128
#define BK 32
#define NITER (HH / BK)   // 32
#define ST 4              // cp.async pipeline stages
#define NTILE_N (HH / BN) // 8
#define NSM 148

// per stage: A 64x128B (2048 f) + B 32x512B (4096 f) = 24KB
#define STAGE_FLOATS 6144
#define SMEM_GEMM_BYTES (ST * STAGE_FLOATS * 4 + BM * 8 + 64)  // ~98.9KB

// route_cvt block segments
#define RB_ROUTE (BB / 8)                  // 1024 routing blocks
#define RB_CVT   (EE * HH * HH / 1024)     // 8192 weight-cvt blocks
#define RB_ZERO  (BB * HH / 1024)          // 8192 out-zero blocks

// ---------------------------------------------------------------------------
// Device scratch (no allocation allowed anywhere)
// ---------------------------------------------------------------------------
__device__ int   g_cnt[EE];
__device__ int   g_tile;
__device__ int   g_done;
__device__ int   g_tok[EE * BB];            // packed: tok | (slot << 31)
__device__ float g_wt [EE * BB];
__device__ float g_xc [(size_t)BB * HH];    // 32 MB: tf32-rounded x
__device__ float g_ewc[(size_t)EE * HH * HH]; // 32 MB: tf32-rounded weights

// ---------------------------------------------------------------------------
__device__ __forceinline__ float f2tf32f(float f) {
    uint32_t r;
    asm("cvt.rna.tf32.f32 %0, %1;" : "=r"(r) : "f"(f));
    return __uint_as_float(r);
}

__device__ __forceinline__ void mma_tf32(float* c, const float* a,
                                         float b0, float b1) {
    asm("mma.sync.aligned.m16n8k8.row.col.f32.tf32.tf32.f32 "
        "{%0,%1,%2,%3}, {%4,%5,%6,%7}, {%8,%9}, {%0,%1,%2,%3};"
        : "+f"(c[0]), "+f"(c[1]), "+f"(c[2]), "+f"(c[3])
        : "r"(__float_as_uint(a[0])), "r"(__float_as_uint(a[1])),
          "r"(__float_as_uint(a[2])), "r"(__float_as_uint(a[3])),
          "r"(__float_as_uint(b0)), "r"(__float_as_uint(b1)));
}

__device__ __forceinline__ void cp16(uint32_t dst, const void* src) {
    asm volatile("cp.async.cg.shared.global [%0], [%1], 16;"
                 :: "r"(dst), "l"(src) : "memory");
}
#define CP_COMMIT() asm volatile("cp.async.commit_group;" ::: "memory")
#define CP_WAIT2()  asm volatile("cp.async.wait_group 2;" ::: "memory")
#define CP_WAIT1()  asm volatile("cp.async.wait_group 1;" ::: "memory")
#define CP_WAIT0()  asm volatile("cp.async.wait_group 0;" ::: "memory")

// Two commutative fp32 adds onto an exact-zero base -> bit-deterministic.
__device__ __forceinline__ void red_add_v2(float* p, float a, float b) {
    asm volatile("red.global.add.v2.f32 [%0], {%1, %2};"
                 :: "l"(p), "f"(a), "f"(b) : "memory");
}

__device__ __forceinline__ uint32_t smem_u32(const void* p) {
    uint32_t a;
    asm("{ .reg .u64 t; cvta.to.shared.u64 t, %1; cvt.u32.u64 %0, t; }"
        : "=r"(a) : "l"(p));
    return a;
}

// ---------------------------------------------------------------------------
// Kernel 1: fused routing + weight conversion + output zeroing (independent
// work, block-split; all three complete before the GEMM launch).
// Routing blocks: stage gw (32KB) into smem TRANSPOSED once per block, then
// one warp per token: LDG.128 x + conflict-free LDS.128 gwT. Exact fp32
// logits, top-2 first-occurrence tie-break (jax.lax.top_k), softmax over the
// 2; emits tf32-rounded x. g_cnt zeroed by previous replay's GEMM tail.
// ---------------------------------------------------------------------------
__global__ void __launch_bounds__(256) route_cvt_kernel(
    const float* __restrict__ x, const float* __restrict__ gw,
    const float4* __restrict__ ew, float4* __restrict__ out) {
    if (blockIdx.x >= RB_ROUTE + RB_CVT) {
        size_t i = (size_t)(blockIdx.x - RB_ROUTE - RB_CVT) * 256 + threadIdx.x;
        out[i] = make_float4(0.f, 0.f, 0.f, 0.f);
        return;
    }
    if (blockIdx.x >= RB_ROUTE) {
        size_t i = (size_t)(blockIdx.x - RB_ROUTE) * 256 + threadIdx.x;
        float4 v = ew[i];
        reinterpret_cast<float4*>(g_ewc)[i] =
            make_float4(f2tf32f(v.x), f2tf32f(v.y),
                        f2tf32f(v.z), f2tf32f(v.w));
        return;
    }

    __shared__ float sgw[EE * HH];          // gwT[e][i], 32KB
    {
        const float4* gw4 = reinterpret_cast<const float4*>(gw);
#pragma unroll
        for (int it = 0; it < 8; it++) {
            int idx = it * 256 + threadIdx.x;      // float4 idx in gw
            float4 v = gw4[idx];
            int i  = idx >> 1;
            int e0 = (idx & 1) * 4;
            sgw[(e0 + 0) * HH + i] = v.x;
            sgw[(e0 + 1) * HH + i] = v.y;
            sgw[(e0 + 2) * HH + i] = v.z;
            sgw[(e0 + 3) * HH + i] = v.w;
        }
    }
    __syncthreads();
    const float4* sgw4 = reinterpret_cast<const float4*>(sgw);

    int tok = (blockIdx.x * 256 + threadIdx.x) >> 5;
    int lid = threadIdx.x & 31;

    const float4* xr = reinterpret_cast<const float4*>(x + (size_t)tok * HH);
    float4*       xc = reinterpret_cast<float4*>(g_xc + (size_t)tok * HH);
    float acc[EE];
#pragma unroll
    for (int e = 0; e < EE; e++) acc[e] = 0.f;

#pragma unroll
    for (int it = 0; it < 8; it++) {
        int fi = it * 32 + lid;             // float4 index within the row
        float4 xv = xr[fi];
        xc[fi] = make_float4(f2tf32f(xv.x), f2tf32f(xv.y),
                             f2tf32f(xv.z), f2tf32f(xv.w));
#pragma unroll
        for (int e = 0; e < EE; e++) {
            float4 g = sgw4[e * (HH / 4) + fi];
            acc[e] += xv.x * g.x + xv.y * g.y + xv.z * g.z + xv.w * g.w;
        }
    }
#pragma unroll
    for (int off = 16; off > 0; off >>= 1)
#pragma unroll
        for (int e = 0; e < EE; e++)
            acc[e] += __shfl_xor_sync(0xffffffffu, acc[e], off);

    if (lid == 0) {
        int i0 = 0; float v0 = acc[0];
#pragma unroll
        for (int e = 1; e < EE; e++)
            if (acc[e] > v0) { v0 = acc[e]; i0 = e; }
        int i1 = -1; float v1 = -3.4e38f;
#pragma unroll
        for (int e = 0; e < EE; e++)
            if (e != i0 && acc[e] > v1) { v1 = acc[e]; i1 = e; }
        float ex1 = expf(v1 - v0);
        float inv = 1.0f / (1.0f + ex1);
        int p0 = atomicAdd(&g_cnt[i0], 1);
        g_tok[i0 * BB + p0] = tok;                    // slot 0
        g_wt [i0 * BB + p0] = inv;
        int p1 = atomicAdd(&g_cnt[i1], 1);
        g_tok[i1 * BB + p1] = tok | (int)0x80000000;  // slot 1
        g_wt [i1 * BB + p1] = ex1 * inv;
    }
}

// ---------------------------------------------------------------------------
// Kernel 2: persistent grouped expert GEMM, 2 CTAs/SM with full pipeline
// slack. 128-thread CTA, tile 64x128x(K=1024), 4 warps (2Mx2N, warp tile
// 32x64), cp.async 4-stage / wait_group 2 with explicit tail waits (1, 0).
// Cross-CTA overlap: while one CTA sits at a chunk barrier / tile epilogue,
// the co-resident CTA's MMAs keep the tensor pipe busy.
// XOR-swizzled natural-layout smem (verified R4/R12 constants):
//   A smem: [row 0..63][128B],  16B-granule g -> g ^ (row&7)
//   B smem: [k 0..31][512B],    granule g -> g ^ ((k&3)<<1)
// Work-stealing over (expert, m-tile, n-tile); epilogue scales by routing
// weight and red.global.add.v2.f32 into out (zeroed by kernel 1; exactly 2
// commutative adds per element -> bit-deterministic). Last exiting CTA
// re-arms counters for the next graph replay.
// ---------------------------------------------------------------------------
__global__ void __launch_bounds__(128, 2)
moe_gemm_kernel(float* __restrict__ out) {
    const float* __restrict__ xc  = g_xc;
    const float* __restrict__ ewc = g_ewc;

    extern __shared__ float smf[];
    uint32_t sbase = smem_u32(smf);
    int*   s_pack = reinterpret_cast<int*>(smf + ST * STAGE_FLOATS);
    float* s_w    = reinterpret_cast<float*>(s_pack + BM);
    int*   s_pfx  = reinterpret_cast<int*>(s_w + BM);   // 9 ints
    int*   s_t    = s_pfx + 9;

    int tid  = threadIdx.x;
    int lane = tid & 31;
    int w    = tid >> 5;
    int wm   = w >> 1;      // 0..1 (M, 32 rows each)
    int wn   = w & 1;       // 0..1 (N, 64 cols each)

    if (tid == 0) {
        int a = 0; s_pfx[0] = 0;
#pragma unroll
        for (int e = 0; e < EE; e++) {
            a += ((g_cnt[e] + BM - 1) / BM) * NTILE_N;
            s_pfx[e + 1] = a;
        }
    }
    __syncthreads();
    int total = s_pfx[EE];

    // consumer fragment constants
    int r = lane >> 2, c = lane & 3;
    int fa0 = wm * 1024 + r * 32 + c;       // A: (wm*32 rows) * 32f + ...
    int fb0 = c * 128 + (r & 3);            // B: k*(128f) + (n&3)
    int offnt[8];
#pragma unroll
    for (int nt = 0; nt < 8; nt++)
        offnt[nt] = ((wn * 16 + nt * 2 + (r >> 2)) ^ (2 * c)) << 2;

    for (;;) {
        if (tid == 0) *s_t = atomicAdd(&g_tile, 1);
        __syncthreads();                 // broadcast t; prev epilogue closed
        int t = *s_t;
        if (t >= total) break;

        // decode t -> (e, m0, n0); n-inner so concurrent tiles share A slab
        int e = 0;
        while (t >= s_pfx[e + 1]) e++;
        int tl   = t - s_pfx[e];
        int m0   = (tl >> 3) * BM;
        int n0   = (tl & 7) * BN;
        int cnt  = g_cnt[e];
        int rows = min(BM, cnt - m0);

        if (tid < BM) {
            int idx = m0 + tid;
            if (idx < cnt) {
                s_pack[tid] = g_tok[e * BB + idx];
                s_w[tid]    = g_wt [e * BB + idx];
            } else {
                s_pack[tid] = 0;
                s_w[tid]    = 0.f;
            }
        }
        __syncthreads();

        // ---- producer address setup (12 cp16 per thread per chunk) ----
        // A: thread t covers rows {p*16 + t>>3}, granule g = t&7 (16B)
        const float* asrc[4];
        uint32_t     adst[4];
        {
            int g = tid & 7, lr = tid >> 3;
#pragma unroll
            for (int p = 0; p < 4; p++) {
                int row = p * 16 + lr;
                int tk  = s_pack[row] & 0x7fffffff;
                asrc[p] = xc + (size_t)tk * HH + g * 4;
                adst[p] = (uint32_t)(row * 128 + ((g ^ (row & 7)) << 4));
            }
        }
        // B: thread t covers k = t>>2, granules (t&3)*8 + j (j 0..7)
        const float* bsrc;
        uint32_t     bdst[8];
        {
            int k = tid >> 2, gq0 = (tid & 3) * 8;
            bsrc = ewc + (size_t)e * HH * HH + (size_t)k * HH + n0 + gq0 * 4;
            int bx = (k & 3) << 1;
#pragma unroll
            for (int j = 0; j < 8; j++)
                bdst[j] = (uint32_t)(8192 + k * 512 + (((gq0 + j) ^ bx) << 4));
        }

        auto produce = [&](int kc) {
            uint32_t sb = sbase + (uint32_t)(kc & (ST - 1)) * (STAGE_FLOATS * 4);
#pragma unroll
            for (int p = 0; p < 4; p++) cp16(sb + adst[p], asrc[p] + kc * BK);
            const float* bs = bsrc + (size_t)kc * BK * HH;
#pragma unroll
            for (int j = 0; j < 8; j++) cp16(sb + bdst[j], bs + j * 4);
            CP_COMMIT();
        };

        float acc[2][8][4];
#pragma unroll
        for (int mt = 0; mt < 2; mt++)
#pragma unroll
            for (int nt = 0; nt < 8; nt++)
#pragma unroll
                for (int q = 0; q < 4; q++) acc[mt][nt][q] = 0.f;

        produce(0); produce(1); produce(2);

        for (int kc = 0; kc < NITER; kc++) {
            if (kc < NITER - 2)       CP_WAIT2();
            else if (kc == NITER - 2) CP_WAIT1();
            else                      CP_WAIT0();
            __syncthreads();
            if (kc + (ST - 1) < NITER) produce(kc + (ST - 1));

            const float* As = smf + (kc & (ST - 1)) * STAGE_FLOATS;
            const float* Bs = As + 2048;
#pragma unroll
            for (int s = 0; s < 4; s++) {
                int ax0 = ((2 * s)     ^ r) << 2;
                int ax1 = ((2 * s + 1) ^ r) << 2;
                float a[2][4];
#pragma unroll
                for (int mt = 0; mt < 2; mt++) {
                    a[mt][0] = As[fa0 + mt * 512 +       ax0];
                    a[mt][1] = As[fa0 + mt * 512 + 256 + ax0];
                    a[mt][2] = As[fa0 + mt * 512 +       ax1];
                    a[mt][3] = As[fa0 + mt * 512 + 256 + ax1];
                }
                const float* Bk = Bs + fb0 + s * 1024;  // +8 k-rows per s
#pragma unroll
                for (int nt = 0; nt < 8; nt++) {
                    float b0 = Bk[offnt[nt]];
                    float b1 = Bk[offnt[nt] + 512];     // +4 k-rows
                    mma_tf32(acc[0][nt], a[0], b0, b1);
                    mma_tf32(acc[1][nt], a[1], b0, b1);
                }
            }
        }

        // ---- epilogue: scale by routing weight, red-add into out ----
        int cq = c * 2;
#pragma unroll
        for (int mt = 0; mt < 2; mt++) {
#pragma unroll
            for (int rr = 0; rr < 2; rr++) {
                int mloc = wm * 32 + mt * 16 + r + rr * 8;
                if (mloc >= rows) continue;
                int   tk = s_pack[mloc] & 0x7fffffff;
                float wt = s_w[mloc];
                float* dst = out + (size_t)tk * HH + n0 + wn * 64 + cq;
#pragma unroll
                for (int nt = 0; nt < 8; nt++)
                    red_add_v2(dst + nt * 8,
                               wt * acc[mt][nt][rr * 2 + 0],
                               wt * acc[mt][nt][rr * 2 + 1]);
            }
        }
    }

    // ---- last exiting CTA re-arms counters for the next graph replay ----
    __syncthreads();
    if (tid == 0) {
        int done = atomicAdd(&g_done, 1);
        if (done == (int)gridDim.x - 1) {
#pragma unroll
            for (int e = 0; e < EE; e++) g_cnt[e] = 0;
            g_tile = 0;
            g_done = 0;
        }
    }
}

// ---------------------------------------------------------------------------
extern "C" void kernel_launch(void* const* d_in, const int* in_sizes, int n_in,
                              void* d_out, int out_size) {
    const float* x  = (const float*)d_in[0];   // [8192, 1024]
    const float* gw = (const float*)d_in[1];   // [1024, 8]
    const float* ew = (const float*)d_in[2];   // [8, 1024, 1024]
    float* out = (float*)d_out;                // [8192, 1024]

    cudaFuncSetAttribute(moe_gemm_kernel,
                         cudaFuncAttributeMaxDynamicSharedMemorySize,
                         SMEM_GEMM_BYTES);

    route_cvt_kernel<<<RB_ROUTE + RB_CVT + RB_ZERO, 256>>>(
        x, gw, (const float4*)ew, (float4*)out);
    moe_gemm_kernel<<<2 * NSM, 128, SMEM_GEMM_BYTES>>>(out);
}

// round 14
// speedup vs baseline: 1.7678x; 1.7678x over previous
#include <cuda_runtime.h>
#include <cstdint>

// Problem dims
#define BB 8192
#define HH 1024
#define EE 8

// GEMM tile: 128x256x32, 256 threads, 8 warps (2 M x 4 N), warp tile 64x64
#define BM 128
#define BN 256
#define BK 32
#define NITER (HH / BK)   // 32
#define ST 4              // cp.async pipeline stages
#define NTILE_N (HH / BN) // 4
#define NSM 148

// per stage: A 128x128B (4096 f) + B 32x1024B (8192 f) = 48KB
#define STAGE_FLOATS 12288
#define SMEM_GEMM_BYTES (ST * STAGE_FLOATS * 4 + BM * 8 + 64)

// route_cvt block segments (weight-cvt segment REMOVED: raw fp32 weights feed
// the tf32 MMA directly; HW truncates low mantissa bits)
#define RB_ROUTE (BB / 8)                  // 1024 routing blocks
#define RB_ZERO  (BB * HH / 1024)          // 8192 out-zero blocks

// ---------------------------------------------------------------------------
// Device scratch (no allocation allowed anywhere)
// ---------------------------------------------------------------------------
__device__ int   g_cnt[EE];
__device__ int   g_tile;
__device__ int   g_done;
__device__ int   g_tok[EE * BB];            // packed: tok | (slot << 31)
__device__ float g_wt [EE * BB];
__device__ float g_xc [(size_t)BB * HH];    // 32 MB: tf32-rounded x

// ---------------------------------------------------------------------------
__device__ __forceinline__ float f2tf32f(float f) {
    uint32_t r;
    asm("cvt.rna.tf32.f32 %0, %1;" : "=r"(r) : "f"(f));
    return __uint_as_float(r);
}

__device__ __forceinline__ void mma_tf32(float* c, const float* a,
                                         float b0, float b1) {
    asm("mma.sync.aligned.m16n8k8.row.col.f32.tf32.tf32.f32 "
        "{%0,%1,%2,%3}, {%4,%5,%6,%7}, {%8,%9}, {%0,%1,%2,%3};"
        : "+f"(c[0]), "+f"(c[1]), "+f"(c[2]), "+f"(c[3])
        : "r"(__float_as_uint(a[0])), "r"(__float_as_uint(a[1])),
          "r"(__float_as_uint(a[2])), "r"(__float_as_uint(a[3])),
          "r"(__float_as_uint(b0)), "r"(__float_as_uint(b1)));
}

__device__ __forceinline__ void cp16(uint32_t dst, const void* src) {
    asm volatile("cp.async.cg.shared.global [%0], [%1], 16;"
                 :: "r"(dst), "l"(src) : "memory");
}
#define CP_COMMIT() asm volatile("cp.async.commit_group;" ::: "memory")
#define CP_WAIT2()  asm volatile("cp.async.wait_group 2;" ::: "memory")
#define CP_WAIT1()  asm volatile("cp.async.wait_group 1;" ::: "memory")
#define CP_WAIT0()  asm volatile("cp.async.wait_group 0;" ::: "memory")

// Two commutative fp32 adds onto an exact-zero base -> bit-deterministic.
__device__ __forceinline__ void red_add_v2(float* p, float a, float b) {
    asm volatile("red.global.add.v2.f32 [%0], {%1, %2};"
                 :: "l"(p), "f"(a), "f"(b) : "memory");
}

__device__ __forceinline__ uint32_t smem_u32(const void* p) {
    uint32_t a;
    asm("{ .reg .u64 t; cvta.to.shared.u64 t, %1; cvt.u32.u64 %0, t; }"
        : "=r"(a) : "l"(p));
    return a;
}

// ---------------------------------------------------------------------------
// Kernel 1: fused routing + output zeroing (independent work, block-split).
// Routing blocks: stage gw (32KB) into smem TRANSPOSED once per block, then
// one warp per token: LDG.128 x + conflict-free LDS.128 gwT. Exact fp32
// logits, top-2 first-occurrence tie-break (jax.lax.top_k), softmax over the
// 2; emits tf32-rounded x. g_cnt zeroed by previous replay's GEMM tail.
// ---------------------------------------------------------------------------
__global__ void __launch_bounds__(256) route_cvt_kernel(
    const float* __restrict__ x, const float* __restrict__ gw,
    float4* __restrict__ out) {
    if (blockIdx.x >= RB_ROUTE) {
        size_t i = (size_t)(blockIdx.x - RB_ROUTE) * 256 + threadIdx.x;
        out[i] = make_float4(0.f, 0.f, 0.f, 0.f);
        return;
    }

    __shared__ float sgw[EE * HH];          // gwT[e][i], 32KB
    {
        const float4* gw4 = reinterpret_cast<const float4*>(gw);
#pragma unroll
        for (int it = 0; it < 8; it++) {
            int idx = it * 256 + threadIdx.x;      // float4 idx in gw
            float4 v = gw4[idx];
            int i  = idx >> 1;
            int e0 = (idx & 1) * 4;
            sgw[(e0 + 0) * HH + i] = v.x;
            sgw[(e0 + 1) * HH + i] = v.y;
            sgw[(e0 + 2) * HH + i] = v.z;
            sgw[(e0 + 3) * HH + i] = v.w;
        }
    }
    __syncthreads();
    const float4* sgw4 = reinterpret_cast<const float4*>(sgw);

    int tok = (blockIdx.x * 256 + threadIdx.x) >> 5;
    int lid = threadIdx.x & 31;

    const float4* xr = reinterpret_cast<const float4*>(x + (size_t)tok * HH);
    float4*       xc = reinterpret_cast<float4*>(g_xc + (size_t)tok * HH);
    float acc[EE];
#pragma unroll
    for (int e = 0; e < EE; e++) acc[e] = 0.f;

#pragma unroll
    for (int it = 0; it < 8; it++) {
        int fi = it * 32 + lid;             // float4 index within the row
        float4 xv = xr[fi];
        xc[fi] = make_float4(f2tf32f(xv.x), f2tf32f(xv.y),
                             f2tf32f(xv.z), f2tf32f(xv.w));
#pragma unroll
        for (int e = 0; e < EE; e++) {
            float4 g = sgw4[e * (HH / 4) + fi];
            acc[e] += xv.x * g.x + xv.y * g.y + xv.z * g.z + xv.w * g.w;
        }
    }
#pragma unroll
    for (int off = 16; off > 0; off >>= 1)
#pragma unroll
        for (int e = 0; e < EE; e++)
            acc[e] += __shfl_xor_sync(0xffffffffu, acc[e], off);

    if (lid == 0) {
        int i0 = 0; float v0 = acc[0];
#pragma unroll
        for (int e = 1; e < EE; e++)
            if (acc[e] > v0) { v0 = acc[e]; i0 = e; }
        int i1 = -1; float v1 = -3.4e38f;
#pragma unroll
        for (int e = 0; e < EE; e++)
            if (e != i0 && acc[e] > v1) { v1 = acc[e]; i1 = e; }
        float ex1 = expf(v1 - v0);
        float inv = 1.0f / (1.0f + ex1);
        int p0 = atomicAdd(&g_cnt[i0], 1);
        g_tok[i0 * BB + p0] = tok;                    // slot 0
        g_wt [i0 * BB + p0] = inv;
        int p1 = atomicAdd(&g_cnt[i1], 1);
        g_tok[i1 * BB + p1] = tok | (int)0x80000000;  // slot 1
        g_wt [i1 * BB + p1] = ex1 * inv;
    }
}

// ---------------------------------------------------------------------------
// Kernel 2: persistent grouped expert GEMM (R12 structure — best measured).
// B is fed RAW fp32: the tf32 MMA hardware truncates the low mantissa bits
// (RZ); only A keeps RNA rounding. This removes the 64MB weight-conversion
// pass entirely. Warp partition 2M x 4N (warp tile 64x64).
// Pipeline: 4-stage cp.async, wait_group 2 with explicit tail waits (1, 0);
// work-stealing over (expert, m, n) tiles.
// XOR-swizzled natural-layout smem (conflict-free LDS.32, verified):
//   A smem: [row 0..127][128B], 16B-granule g -> g ^ (row&7)
//   B smem: [k 0..31][1024B],   granule g -> g ^ ((k&3)<<1)
// Epilogue: scale by routing weight, red.global.add.v2.f32 into out (zeroed
// by kernel 1; exactly 2 commutative adds per element -> bit-deterministic).
// Last exiting CTA re-arms counters for the next graph replay.
// ---------------------------------------------------------------------------
__global__ void __launch_bounds__(256, 1)
moe_gemm_kernel(float* __restrict__ out, const float* __restrict__ ew) {
    const float* __restrict__ xc = g_xc;

    extern __shared__ float smf[];
    uint32_t sbase = smem_u32(smf);
    int*   s_pack = reinterpret_cast<int*>(smf + ST * STAGE_FLOATS);
    float* s_w    = reinterpret_cast<float*>(s_pack + BM);
    int*   s_pfx  = reinterpret_cast<int*>(s_w + BM);   // 9 ints
    int*   s_t    = s_pfx + 9;

    int tid  = threadIdx.x;
    int lane = tid & 31;
    int w    = tid >> 5;
    int wm   = w >> 2;      // 0..1 (M, 64 rows each)
    int wn   = w & 3;       // 0..3 (N, 64 cols each)

    if (tid == 0) {
        int a = 0; s_pfx[0] = 0;
#pragma unroll
        for (int e = 0; e < EE; e++) {
            a += ((g_cnt[e] + BM - 1) / BM) * NTILE_N;
            s_pfx[e + 1] = a;
        }
    }
    __syncthreads();
    int total = s_pfx[EE];

    // consumer fragment constants
    int r = lane >> 2, c = lane & 3;
    int fa0 = wm * 2048 + r * 32 + c;       // A: row*(32f); wm*64 rows base
    int fb0 = c * 256 + (r & 3);            // B: k*(256f) + (n&3)
    int offnt[8];
#pragma unroll
    for (int nt = 0; nt < 8; nt++)
        offnt[nt] = ((wn * 16 + nt * 2 + (r >> 2)) ^ (2 * c)) << 2;

    for (;;) {
        if (tid == 0) *s_t = atomicAdd(&g_tile, 1);
        __syncthreads();                 // broadcast t; prev epilogue closed
        int t = *s_t;
        if (t >= total) break;

        // decode t -> (e, m0, n0); n-inner so concurrent tiles share A slab
        int e = 0;
        while (t >= s_pfx[e + 1]) e++;
        int tl   = t - s_pfx[e];
        int m0   = (tl >> 2) * BM;
        int n0   = (tl & 3) * BN;
        int cnt  = g_cnt[e];
        int rows = min(BM, cnt - m0);

        if (tid < BM) {
            int idx = m0 + tid;
            if (idx < cnt) {
                s_pack[tid] = g_tok[e * BB + idx];
                s_w[tid]    = g_wt [e * BB + idx];
            } else {
                s_pack[tid] = 0;
                s_w[tid]    = 0.f;
            }
        }
        __syncthreads();

        // ---- producer address setup ----
        // A: thread t covers rows {p*32 + t>>3}, granule g = t&7 (16B)
        const float* asrc[4];
        uint32_t     adst[4];
        {
            int g = tid & 7, lr = tid >> 3;
#pragma unroll
            for (int p = 0; p < 4; p++) {
                int row = p * 32 + lr;
                int tk  = s_pack[row] & 0x7fffffff;
                asrc[p] = xc + (size_t)tk * HH + g * 4;
                adst[p] = (uint32_t)(row * 128 + ((g ^ (lr & 7)) << 4));
            }
        }
        // B: thread t covers k rows {p*8 + t>>5}, granules t&31 and +32
        const float* bsrc[4];
        uint32_t     bdst[4];
        {
            int gB = tid & 31, k0 = tid >> 5;
#pragma unroll
            for (int p = 0; p < 4; p++) {
                int k = p * 8 + k0;
                bsrc[p] = ew + (size_t)e * HH * HH + (size_t)k * HH
                        + n0 + gB * 4;
                bdst[p] = (uint32_t)(16384 + k * 1024 +
                                     ((gB ^ ((k0 & 3) << 1)) << 4));
            }
        }

        auto produce = [&](int kc) {
            uint32_t sb = sbase + (uint32_t)(kc & (ST - 1)) * (STAGE_FLOATS * 4);
#pragma unroll
            for (int p = 0; p < 4; p++) cp16(sb + adst[p], asrc[p] + kc * BK);
#pragma unroll
            for (int p = 0; p < 4; p++) {
                const float* s = bsrc[p] + (size_t)kc * BK * HH;
                cp16(sb + bdst[p], s);
                cp16(sb + bdst[p] + 512, s + 128);
            }
            CP_COMMIT();
        };

        float acc[4][8][4];
#pragma unroll
        for (int mt = 0; mt < 4; mt++)
#pragma unroll
            for (int nt = 0; nt < 8; nt++)
#pragma unroll
                for (int q = 0; q < 4; q++) acc[mt][nt][q] = 0.f;

        produce(0); produce(1); produce(2);

        for (int kc = 0; kc < NITER; kc++) {
            if (kc < NITER - 2)       CP_WAIT2();
            else if (kc == NITER - 2) CP_WAIT1();
            else                      CP_WAIT0();
            __syncthreads();
            if (kc + (ST - 1) < NITER) produce(kc + (ST - 1));

            const float* As = smf + (kc & (ST - 1)) * STAGE_FLOATS;
            const float* Bs = As + 4096;
#pragma unroll
            for (int s = 0; s < 4; s++) {
                int ax0 = ((2 * s)     ^ r) << 2;
                int ax1 = ((2 * s + 1) ^ r) << 2;
                float a[4][4];
#pragma unroll
                for (int mt = 0; mt < 4; mt++) {
                    a[mt][0] = As[fa0 + mt * 512 +       ax0];
                    a[mt][1] = As[fa0 + mt * 512 + 256 + ax0];
                    a[mt][2] = As[fa0 + mt * 512 +       ax1];
                    a[mt][3] = As[fa0 + mt * 512 + 256 + ax1];
                }
                const float* Bk = Bs + fb0 + s * 2048;  // +8 k-rows per s
#pragma unroll
                for (int nt = 0; nt < 8; nt++) {
                    float b0 = Bk[offnt[nt]];
                    float b1 = Bk[offnt[nt] + 1024];    // +4 k-rows
#pragma unroll
                    for (int mt = 0; mt < 4; mt++)
                        mma_tf32(acc[mt][nt], a[mt], b0, b1);
                }
            }
        }

        // ---- epilogue: scale by routing weight, red-add into out ----
        int cq = c * 2;
#pragma unroll
        for (int mt = 0; mt < 4; mt++) {
#pragma unroll
            for (int rr = 0; rr < 2; rr++) {
                int mloc = wm * 64 + mt * 16 + r + rr * 8;
                if (mloc >= rows) continue;
                int   tk = s_pack[mloc] & 0x7fffffff;
                float wt = s_w[mloc];
                float* dst = out + (size_t)tk * HH + n0 + wn * 64 + cq;
#pragma unroll
                for (int nt = 0; nt < 8; nt++)
                    red_add_v2(dst + nt * 8,
                               wt * acc[mt][nt][rr * 2 + 0],
                               wt * acc[mt][nt][rr * 2 + 1]);
            }
        }
    }

    // ---- last exiting CTA re-arms counters for the next graph replay ----
    __syncthreads();
    if (tid == 0) {
        int done = atomicAdd(&g_done, 1);
        if (done == (int)gridDim.x - 1) {
#pragma unroll
            for (int e = 0; e < EE; e++) g_cnt[e] = 0;
            g_tile = 0;
            g_done = 0;
        }
    }
}

// ---------------------------------------------------------------------------
extern "C" void kernel_launch(void* const* d_in, const int* in_sizes, int n_in,
                              void* d_out, int out_size) {
    const float* x  = (const float*)d_in[0];   // [8192, 1024]
    const float* gw = (const float*)d_in[1];   // [1024, 8]
    const float* ew = (const float*)d_in[2];   // [8, 1024, 1024]
    float* out = (float*)d_out;                // [8192, 1024]

    cudaFuncSetAttribute(moe_gemm_kernel,
                         cudaFuncAttributeMaxDynamicSharedMemorySize,
                         SMEM_GEMM_BYTES);

    route_cvt_kernel<<<RB_ROUTE + RB_ZERO, 256>>>(x, gw, (float4*)out);
    moe_gemm_kernel<<<NSM, 256, SMEM_GEMM_BYTES>>>(out, ew);
}